// round 2
// baseline (speedup 1.0000x reference)
#include <cuda_runtime.h>
#include <math.h>

// Problem constants (match reference)
#define N_INPUTS 2048
#define UNITS    2048
#define L        8
#define FANIN    4096
#define TOTAL    (N_INPUTS + L * UNITS)   // 18432

// GEMV decomposition
#define KSPLIT   32
#define KCHUNK   (FANIN / KSPLIT)         // 128
#define UTILE    128                      // threads per block, 1 unit each

// Scratch (device globals: allocation-free per harness rules)
__device__ float g_state[TOTAL];                 // shared "outputs" vector
__device__ float g_partial[KSPLIT * UNITS];      // split-K partial sums

// Zero the state vector and write x into segment 0.
__global__ void init_kernel(const float* __restrict__ x) {
    int i = blockIdx.x * blockDim.x + threadIdx.x;
    if (i < TOTAL) {
        g_state[i] = (i < N_INPUTS) ? x[i] : 0.0f;
    }
}

// One layer's GEMV partial: block (bx, by) computes, for units
// u in [bx*UTILE, bx*UTILE+UTILE) and k in [by*KCHUNK, (by+1)*KCHUNK):
//   partial[by][u] = sum_k gather(state, inds[k]) * W[k][u]
// W reads are fully coalesced (consecutive u across the warp at fixed k).
__global__ __launch_bounds__(UTILE) void gemv_partial_kernel(
    const float* __restrict__ W,      // [FANIN, UNITS] for this layer
    const int*   __restrict__ inds)   // [FANIN] for this layer
{
    __shared__ float gs[KCHUNK];

    const int u  = blockIdx.x * UTILE + threadIdx.x;
    const int k0 = blockIdx.y * KCHUNK;

    // Gather this K-chunk of the input vector into shared memory.
    if (threadIdx.x < KCHUNK) {
        gs[threadIdx.x] = g_state[inds[k0 + threadIdx.x]];
    }
    __syncthreads();

    float acc = 0.0f;
    const float* Wp = W + (size_t)k0 * UNITS + u;
    #pragma unroll 8
    for (int k = 0; k < KCHUNK; ++k) {
        acc = fmaf(gs[k], Wp[(size_t)k * UNITS], acc);
    }

    g_partial[blockIdx.y * UNITS + u] = acc;
}

// Reduce the KSPLIT partials, add bias, tanh, write into the state vector
// (segment for the NEXT layer's gather) and, on the last layer, to d_out.
__global__ void finalize_kernel(const float* __restrict__ b,
                                int seg_offset,
                                float* __restrict__ out /* may be null */)
{
    const int u = blockIdx.x * blockDim.x + threadIdx.x;
    float acc = b[u];
    #pragma unroll
    for (int s = 0; s < KSPLIT; ++s) {
        acc += g_partial[s * UNITS + u];
    }
    const float v = tanhf(acc);
    g_state[seg_offset + u] = v;
    if (out) out[u] = v;
}

extern "C" void kernel_launch(void* const* d_in, const int* in_sizes, int n_in,
                              void* d_out, int out_size) {
    const float* x         = (const float*)d_in[0];  // [2048] f32
    const int*   node_inds = (const int*)  d_in[1];  // [L, FANIN] i32
    const float* Ws        = (const float*)d_in[2];  // [L, FANIN, UNITS] f32
    const float* bs        = (const float*)d_in[3];  // [L, UNITS] f32
    float*       out       = (float*)d_out;          // [2048] f32

    init_kernel<<<(TOTAL + 255) / 256, 256>>>(x);

    for (int i = 0; i < L; ++i) {
        const float* Wi = Ws + (size_t)i * FANIN * UNITS;
        const int*   Ii = node_inds + i * FANIN;
        const float* bi = bs + i * UNITS;

        dim3 grid(UNITS / UTILE, KSPLIT);
        gemv_partial_kernel<<<grid, UTILE>>>(Wi, Ii);

        // Layer i's output occupies state segment (i+1); segment 8 exists
        // (TOTAL = 9*2048) and is harmlessly written for the last layer.
        const int seg = (i + 1) * UNITS;
        finalize_kernel<<<UNITS / 256, 256>>>(bi, seg, (i == L - 1) ? out : nullptr);
    }
}

// round 3
// speedup vs baseline: 1.3212x; 1.3212x over previous
#include <cuda_runtime.h>
#include <math.h>

// Problem constants (match reference)
#define N_INPUTS 2048
#define UNITS    2048
#define L        8
#define FANIN    4096
#define TOTAL    (N_INPUTS + L * UNITS)   // 18432

// GEMV decomposition
#define KSPLIT   128
#define KCHUNK   (FANIN / KSPLIT)         // 32
#define TPB      256                      // threads per gemv block
#define U_PER_T  4                        // each thread owns one float4 of units
#define U_BLK    (TPB * U_PER_T)          // 1024 units per block
#define U_TILES  (UNITS / U_BLK)          // 2

// Scratch (device globals: allocation-free per harness rules)
__device__ float g_state[TOTAL];                 // shared "outputs" vector
__device__ float g_partial[KSPLIT * UNITS];      // split-K partial sums

// Zero the state vector and write x into segment 0.
__global__ void init_kernel(const float* __restrict__ x) {
    int i = blockIdx.x * blockDim.x + threadIdx.x;
    if (i < TOTAL) {
        g_state[i] = (i < N_INPUTS) ? x[i] : 0.0f;
    }
}

// One layer's GEMV partial. Block (ub, kb):
//   units u4 = (ub*TPB + tid) -> 4 consecutive units via float4
//   k in [kb*KCHUNK, (kb+1)*KCHUNK)
// W rows are read as float4: warp covers 32*16B = 512 contiguous bytes per k,
// fully coalesced. KCHUNK is fully unrolled so ptxas can front-batch many
// independent float4 LDG.128s -> deep MLP -> DRAM-latency hidden.
__global__ __launch_bounds__(TPB) void gemv_partial_kernel(
    const float* __restrict__ W,      // [FANIN, UNITS] for this layer
    const int*   __restrict__ inds)   // [FANIN] for this layer
{
    __shared__ float gs[KCHUNK];

    const int tid = threadIdx.x;
    const int u4  = blockIdx.x * TPB + tid;          // float4 column index
    const int k0  = blockIdx.y * KCHUNK;

    if (tid < KCHUNK) {
        gs[tid] = g_state[inds[k0 + tid]];
    }
    __syncthreads();

    const float4* Wp = reinterpret_cast<const float4*>(W + (size_t)k0 * UNITS) + u4;

    float4 acc = make_float4(0.f, 0.f, 0.f, 0.f);
    #pragma unroll
    for (int k = 0; k < KCHUNK; ++k) {
        const float  s = gs[k];
        const float4 w = Wp[(size_t)k * (UNITS / 4)];
        acc.x = fmaf(s, w.x, acc.x);
        acc.y = fmaf(s, w.y, acc.y);
        acc.z = fmaf(s, w.z, acc.z);
        acc.w = fmaf(s, w.w, acc.w);
    }

    float4* pp = reinterpret_cast<float4*>(g_partial + (size_t)blockIdx.y * UNITS) + u4;
    *pp = acc;
}

// Warp-per-unit reduction of the KSPLIT partials + bias + tanh.
// Block = 256 threads = 8 warps -> 8 units per block; grid = UNITS/8 = 256.
// Lane l of the unit's warp sums partials s = l, l+32, l+64, l+96 (KSPLIT=128).
__global__ __launch_bounds__(256) void finalize_kernel(
    const float* __restrict__ b,
    int seg_offset,
    float* __restrict__ out /* may be null */)
{
    const int warp = threadIdx.x >> 5;
    const int lane = threadIdx.x & 31;
    const int u    = blockIdx.x * 8 + warp;

    float acc = 0.0f;
    #pragma unroll
    for (int s = lane; s < KSPLIT; s += 32) {
        acc += g_partial[(size_t)s * UNITS + u];
    }
    #pragma unroll
    for (int off = 16; off > 0; off >>= 1) {
        acc += __shfl_xor_sync(0xFFFFFFFFu, acc, off);
    }

    if (lane == 0) {
        const float v = tanhf(acc + b[u]);
        g_state[seg_offset + u] = v;
        if (out) out[u] = v;
    }
}

extern "C" void kernel_launch(void* const* d_in, const int* in_sizes, int n_in,
                              void* d_out, int out_size) {
    const float* x         = (const float*)d_in[0];  // [2048] f32
    const int*   node_inds = (const int*)  d_in[1];  // [L, FANIN] i32
    const float* Ws        = (const float*)d_in[2];  // [L, FANIN, UNITS] f32
    const float* bs        = (const float*)d_in[3];  // [L, UNITS] f32
    float*       out       = (float*)d_out;          // [2048] f32

    init_kernel<<<(TOTAL + 255) / 256, 256>>>(x);

    for (int i = 0; i < L; ++i) {
        const float* Wi = Ws + (size_t)i * FANIN * UNITS;
        const int*   Ii = node_inds + i * FANIN;
        const float* bi = bs + i * UNITS;

        dim3 grid(U_TILES, KSPLIT);                  // 2 x 128 = 256 blocks
        gemv_partial_kernel<<<grid, TPB>>>(Wi, Ii);

        const int seg = (i + 1) * UNITS;             // segment 8 exists; harmless
        finalize_kernel<<<UNITS / 8, 256>>>(bi, seg, (i == L - 1) ? out : nullptr);
    }
}